// round 6
// baseline (speedup 1.0000x reference)
#include <cuda_runtime.h>
#include <cstdint>

// 2-bit quantized embedding lookup.
// ids: [262144] (int32 OR int64 — detected at runtime), bit_arr: [3.2M] int32,
// codebook: [4] float. Each token's 128 2-bit codes = 256 bits = 8 aligned
// int32 words at bit_arr[token*8].
// Thread layout: 8 threads per token, each decodes one word (16 dims -> 64B out).
// Output per token = 512B contiguous across its 8 lanes -> coalesced STG.128.
// bit_arr (12.8MB) is L2-resident; kernel is output-write-bandwidth bound.

__device__ int g_id_stride;   // 1 if ids are int32, 2 if ids are int64 (low word)

// Detect id dtype: for int64 (nonneg, < 2^31) every odd 32-bit word is zero.
// For int32, odd words are random ids (~0 chance all zero). Deterministic.
__global__ void detect_id_stride_kernel(const unsigned* __restrict__ w32)
{
    __shared__ int any_nonzero;
    if (threadIdx.x == 0) any_nonzero = 0;
    __syncthreads();
    // scan odd words 1,3,...,2047 (covers first 1024 elements either way;
    // buffer has >= 262144 elements * >=4B, so in-bounds).
    unsigned acc = 0;
    for (int i = threadIdx.x; i < 1024; i += blockDim.x)
        acc |= w32[2 * i + 1];
    if (acc) atomicOr(&any_nonzero, 1);
    __syncthreads();
    if (threadIdx.x == 0)
        g_id_stride = any_nonzero ? 1 : 2;   // nonzero odd words => int32
}

__global__ void __launch_bounds__(256) embed2b_kernel(
    const unsigned* __restrict__ idw,   // ids viewed as 32-bit words
    const int*      __restrict__ bits,
    const float*    __restrict__ cb,
    float4*         __restrict__ out,
    int n_tokens)
{
    int gt = blockIdx.x * blockDim.x + threadIdx.x;
    int token_idx = gt >> 3;
    int lane      = gt & 7;
    if (token_idx >= n_tokens) return;

    int stride = g_id_stride;           // L1-broadcast read, uniform

    // Codebook: 4 floats, L1-broadcast hits.
    float c0 = __ldg(cb + 0);
    float c1 = __ldg(cb + 1);
    float c2 = __ldg(cb + 2);
    float c3 = __ldg(cb + 3);

    // little-endian: low 32-bit word holds the full id in either layout
    unsigned tok = __ldg(idw + (size_t)token_idx * stride);
    unsigned widx = tok * 8u + (unsigned)lane;        // max 400000*8 = 3.2M
    unsigned w = (unsigned)__ldg(bits + widx);        // 16 codes in this word

    float4* o = out + (size_t)token_idx * 32 + (size_t)lane * 4;

    #pragma unroll
    for (int k = 0; k < 4; k++) {
        float4 v;
        // dims 4k..4k+3 -> shifts 8k, 8k+2, 8k+4, 8k+6
        {
            unsigned code = (w >> (8 * k + 0)) & 3u;
            float a = (code & 1u) ? c1 : c0;
            float b = (code & 1u) ? c3 : c2;
            v.x = (code & 2u) ? b : a;
        }
        {
            unsigned code = (w >> (8 * k + 2)) & 3u;
            float a = (code & 1u) ? c1 : c0;
            float b = (code & 1u) ? c3 : c2;
            v.y = (code & 2u) ? b : a;
        }
        {
            unsigned code = (w >> (8 * k + 4)) & 3u;
            float a = (code & 1u) ? c1 : c0;
            float b = (code & 1u) ? c3 : c2;
            v.z = (code & 2u) ? b : a;
        }
        {
            unsigned code = (w >> (8 * k + 6)) & 3u;
            float a = (code & 1u) ? c1 : c0;
            float b = (code & 1u) ? c3 : c2;
            v.w = (code & 2u) ? b : a;
        }
        o[k] = v;
    }
}

extern "C" void kernel_launch(void* const* d_in, const int* in_sizes, int n_in,
                              void* d_out, int out_size)
{
    const unsigned* idw  = (const unsigned*)d_in[0];  // ids (int32 or int64)
    const int*      bits = (const int*)d_in[1];       // packed 2-bit codes
    const float*    cb   = (const float*)d_in[2];     // 4-entry codebook
    float*          out  = (float*)d_out;             // [N, 128] fp32

    int n_tokens = in_sizes[0];                        // 64*4096 = 262144

    detect_id_stride_kernel<<<1, 256>>>(idw);

    int total_threads = n_tokens * 8;
    int block = 256;
    int grid = (total_threads + block - 1) / block;
    embed2b_kernel<<<grid, block>>>(idw, bits, cb, (float4*)out, n_tokens);
}